// round 13
// baseline (speedup 1.0000x reference)
#include <cuda_runtime.h>
#include <cuda_bf16.h>
#include <cstdint>

// Problem constants
#define BB    16
#define CIN   128
#define COUT  128
#define NN    4096
#define KNBR  16      // neighbors per node (plus self -> deg 17)
#define TILE_N 128    // n-tile per GEMM block
#define KC    16      // k-chunk for GEMM

// Scratch: h stored TRANSPOSED as [b][n][c] so the gather reads 512B
// contiguous channel rows. 16*4096*128 floats = 33.5 MB (fits L2).
__device__ __align__(16) float g_h[(size_t)BB * NN * COUT];

// ---------------------------------------------------------------------------
// Kernel 1: h[b][n][c] = relu( sum_i W[c][i] * x[b][i][n] )
// Register-blocked fp32 GEMM using packed fma.rn.f32x2 (2 n-values per reg).
// Block: 256 threads, computes a 128(c) x 128(n) tile for one batch.
// ---------------------------------------------------------------------------
__global__ void __launch_bounds__(256)
gemm_relu_kernel(const float* __restrict__ x, const float* __restrict__ W)
{
    // Wd holds (w,w) pre-packed pairs so the inner loop is pure LDS + f32x2 FMA.
    // Row padded to 129 to kill the 16-way store conflict (2*il mod 32 distinct).
    __shared__ __align__(16) unsigned long long Wd[KC][COUT + 1];
    __shared__ __align__(16) float Xs[KC][TILE_N];

    const int b  = blockIdx.y;
    const int n0 = blockIdx.x * TILE_N;
    const int t  = threadIdx.x;
    const int tc = t >> 4;        // 0..15 -> c block
    const int tn = t & 15;        // 0..15 -> n block
    const int c0  = tc * 8;
    const int nl0 = tn * 8;       // 8 n values = 4 f32x2 pairs

    unsigned long long acc[8][4];
#pragma unroll
    for (int i = 0; i < 8; i++)
#pragma unroll
        for (int p = 0; p < 4; p++) acc[i][p] = 0ull;  // (+0.f, +0.f)

    const float* xb = x + (size_t)b * CIN * NN;

    for (int k0 = 0; k0 < CIN; k0 += KC) {
        // Load + duplicate-pack W chunk: Wd[il][o] = {W[o][k0+il], same}
#pragma unroll
        for (int r = 0; r < 8; r++) {
            int e  = t + 256 * r;        // 0..2047
            int il = e & 15;
            int o  = e >> 4;             // 0..127
            float w = W[o * CIN + k0 + il];
            unsigned long long pk;
            unsigned int wu = __float_as_uint(w);
            asm("mov.b64 %0, {%1, %1};" : "=l"(pk) : "r"(wu));
            Wd[il][o] = pk;
        }
        // Load X chunk: Xs[il][nl] = x[b][k0+il][n0+nl]  (coalesced rows)
#pragma unroll
        for (int r = 0; r < 8; r++) {
            int e  = t + 256 * r;
            int nl = e & 127;
            int il = e >> 7;
            Xs[il][nl] = xb[(size_t)(k0 + il) * NN + n0 + nl];
        }
        __syncthreads();

#pragma unroll
        for (int kk = 0; kk < KC; kk++) {
            unsigned long long wr[8];
#pragma unroll
            for (int i = 0; i < 8; i++) wr[i] = Wd[kk][c0 + i];
            const unsigned long long* xp =
                reinterpret_cast<const unsigned long long*>(&Xs[kk][nl0]);
            unsigned long long xr[4];
#pragma unroll
            for (int p = 0; p < 4; p++) xr[p] = xp[p];
#pragma unroll
            for (int i = 0; i < 8; i++)
#pragma unroll
                for (int p = 0; p < 4; p++)
                    asm("fma.rn.f32x2 %0, %1, %2, %0;"
                        : "+l"(acc[i][p]) : "l"(wr[i]), "l"(xr[p]));
        }
        __syncthreads();
    }

    // Epilogue: relu + store transposed h[b][n][c] (float4 x2 per n row)
    float* hb = g_h + (size_t)b * NN * COUT;
#pragma unroll
    for (int p = 0; p < 4; p++) {
        float lo[8], hi[8];
#pragma unroll
        for (int i = 0; i < 8; i++) {
            unsigned int a, c;
            asm("mov.b64 {%0, %1}, %2;" : "=r"(a), "=r"(c) : "l"(acc[i][p]));
            lo[i] = fmaxf(__uint_as_float(a), 0.0f);
            hi[i] = fmaxf(__uint_as_float(c), 0.0f);
        }
        int ne = n0 + nl0 + 2 * p;
        float4* d0 = reinterpret_cast<float4*>(hb + (size_t)ne * COUT + c0);
        d0[0] = make_float4(lo[0], lo[1], lo[2], lo[3]);
        d0[1] = make_float4(lo[4], lo[5], lo[6], lo[7]);
        float4* d1 = reinterpret_cast<float4*>(hb + (size_t)(ne + 1) * COUT + c0);
        d1[0] = make_float4(hi[0], hi[1], hi[2], hi[3]);
        d1[1] = make_float4(hi[4], hi[5], hi[6], hi[7]);
    }
}

// ---------------------------------------------------------------------------
// Kernel 2: out[b][c][n] = (1/17) * ( sum_{k<16} h[b][:, idx_k] + h[b][:, n] ) + bias[c]
// Warp handles 4 nodes; each lane owns 4 channels (float4) -> gathered rows are
// fully-coalesced 512B reads. Output re-transposed via padded smem tile so the
// [b][c][n] stores are 128B-coalesced along n.
// ---------------------------------------------------------------------------
__global__ void __launch_bounds__(256)
gather_mean_bias_kernel(const int* __restrict__ ei,
                        const float* __restrict__ bias,
                        float* __restrict__ out)
{
    __shared__ __align__(16) float tile[32][132];   // padded: (4i+c)%32 -> <=4-way on read

    const int b    = blockIdx.y;
    const int n0   = blockIdx.x * 32;
    const int t    = threadIdx.x;
    const int lane = t & 31;
    const int w    = t >> 5;                 // warp 0..7, 4 nodes each
    const int nbase = n0 + w * 4;

    const float4* hb = reinterpret_cast<const float4*>(g_h) + (size_t)b * NN * 32;
    const int* eib = ei + (size_t)b * NN * KNBR;   // edge_index[0][b]...

    float4 acc[4];
    int myidx[4];
#pragma unroll
    for (int m = 0; m < 4; m++) {
        acc[m] = make_float4(0.f, 0.f, 0.f, 0.f);
        myidx[m] = (lane < KNBR) ? eib[(size_t)(nbase + m) * KNBR + lane] : 0;
    }

#pragma unroll 4
    for (int k = 0; k < KNBR; k++) {
#pragma unroll
        for (int m = 0; m < 4; m++) {
            int j = __shfl_sync(0xffffffffu, myidx[m], k);
            float4 v = __ldg(&hb[(size_t)j * 32 + lane]);
            acc[m].x += v.x; acc[m].y += v.y; acc[m].z += v.z; acc[m].w += v.w;
        }
    }
    // self loop
#pragma unroll
    for (int m = 0; m < 4; m++) {
        float4 v = __ldg(&hb[(size_t)(nbase + m) * 32 + lane]);
        acc[m].x += v.x; acc[m].y += v.y; acc[m].z += v.z; acc[m].w += v.w;
    }

    const float norm = 1.0f / 17.0f;
    float4 bv = __ldg(reinterpret_cast<const float4*>(bias) + lane);

#pragma unroll
    for (int m = 0; m < 4; m++) {
        float4 r;
        r.x = fmaf(acc[m].x, norm, bv.x);
        r.y = fmaf(acc[m].y, norm, bv.y);
        r.z = fmaf(acc[m].z, norm, bv.z);
        r.w = fmaf(acc[m].w, norm, bv.w);
        *reinterpret_cast<float4*>(&tile[w * 4 + m][lane * 4]) = r;
    }
    __syncthreads();

    // Coalesced write-out: out[b][c][n0..n0+31]
#pragma unroll
    for (int r = 0; r < 16; r++) {
        int e = t + 256 * r;          // 0..4095
        int c = e >> 5;
        int i = e & 31;
        out[((size_t)b * COUT + c) * NN + n0 + i] = tile[i][c];
    }
}

extern "C" void kernel_launch(void* const* d_in, const int* in_sizes, int n_in,
                              void* d_out, int out_size)
{
    const float* x    = (const float*)d_in[0];   // [16,128,4096,1]
    const int*   ei   = (const int*)  d_in[1];   // [2,16,4096,16]
    const float* W    = (const float*)d_in[2];   // [128,128]
    const float* bias = (const float*)d_in[3];   // [1,128,1,1]
    float* out = (float*)d_out;                  // [16,128,4096,1]

    dim3 g1(NN / TILE_N, BB);   // 32 x 16
    gemm_relu_kernel<<<g1, 256>>>(x, W);

    dim3 g2(NN / 32, BB);       // 128 x 16
    gather_mean_bias_kernel<<<g2, 256>>>(ei, bias, out);
}

// round 14
// speedup vs baseline: 1.0141x; 1.0141x over previous
#include <cuda_runtime.h>
#include <cuda_bf16.h>
#include <cstdint>

// Problem constants
#define BB    16
#define CIN   128
#define COUT  128
#define NN    4096
#define KNBR  16      // neighbors per node (plus self -> deg 17)
#define TILE_N 128    // n-tile per GEMM block
#define KC    16      // k-chunk for GEMM

// Scratch: h stored TRANSPOSED as [b][n][c] so the gather reads 512B
// contiguous channel rows. 16*4096*128 floats = 33.5 MB (fits L2).
__device__ __align__(16) float g_h[(size_t)BB * NN * COUT];

// ---------------------------------------------------------------------------
// Kernel 1: h[b][n][c] = relu( sum_i W[c][i] * x[b][i][n] )
// Register-blocked fp32 GEMM using packed fma.rn.f32x2 (2 n-values per reg).
// Block: 256 threads, computes a 128(c) x 128(n) tile for one batch.
// ---------------------------------------------------------------------------
__global__ void __launch_bounds__(256)
gemm_relu_kernel(const float* __restrict__ x, const float* __restrict__ W)
{
    // Wd holds (w,w) pre-packed pairs so the inner loop is pure LDS + f32x2 FMA.
    // Row padded to 129 to kill the 16-way store conflict (2*il mod 32 distinct).
    __shared__ __align__(16) unsigned long long Wd[KC][COUT + 1];
    __shared__ __align__(16) float Xs[KC][TILE_N];

    const int b  = blockIdx.y;
    const int n0 = blockIdx.x * TILE_N;
    const int t  = threadIdx.x;
    const int tc = t >> 4;        // 0..15 -> c block
    const int tn = t & 15;        // 0..15 -> n block
    const int c0  = tc * 8;
    const int nl0 = tn * 8;       // 8 n values = 4 f32x2 pairs

    unsigned long long acc[8][4];
#pragma unroll
    for (int i = 0; i < 8; i++)
#pragma unroll
        for (int p = 0; p < 4; p++) acc[i][p] = 0ull;  // (+0.f, +0.f)

    const float* xb = x + (size_t)b * CIN * NN;

    for (int k0 = 0; k0 < CIN; k0 += KC) {
        // Load + duplicate-pack W chunk: Wd[il][o] = {W[o][k0+il], same}
#pragma unroll
        for (int r = 0; r < 8; r++) {
            int e  = t + 256 * r;        // 0..2047
            int il = e & 15;
            int o  = e >> 4;             // 0..127
            float w = W[o * CIN + k0 + il];
            unsigned long long pk;
            unsigned int wu = __float_as_uint(w);
            asm("mov.b64 %0, {%1, %1};" : "=l"(pk) : "r"(wu));
            Wd[il][o] = pk;
        }
        // Load X chunk: Xs[il][nl] = x[b][k0+il][n0+nl]  (coalesced rows)
#pragma unroll
        for (int r = 0; r < 8; r++) {
            int e  = t + 256 * r;
            int nl = e & 127;
            int il = e >> 7;
            Xs[il][nl] = xb[(size_t)(k0 + il) * NN + n0 + nl];
        }
        __syncthreads();

#pragma unroll
        for (int kk = 0; kk < KC; kk++) {
            unsigned long long wr[8];
#pragma unroll
            for (int i = 0; i < 8; i++) wr[i] = Wd[kk][c0 + i];
            const unsigned long long* xp =
                reinterpret_cast<const unsigned long long*>(&Xs[kk][nl0]);
            unsigned long long xr[4];
#pragma unroll
            for (int p = 0; p < 4; p++) xr[p] = xp[p];
#pragma unroll
            for (int i = 0; i < 8; i++)
#pragma unroll
                for (int p = 0; p < 4; p++)
                    asm("fma.rn.f32x2 %0, %1, %2, %0;"
                        : "+l"(acc[i][p]) : "l"(wr[i]), "l"(xr[p]));
        }
        __syncthreads();
    }

    // Epilogue: relu + store transposed h[b][n][c] (float4 x2 per n row)
    float* hb = g_h + (size_t)b * NN * COUT;
#pragma unroll
    for (int p = 0; p < 4; p++) {
        float lo[8], hi[8];
#pragma unroll
        for (int i = 0; i < 8; i++) {
            unsigned int a, c;
            asm("mov.b64 {%0, %1}, %2;" : "=r"(a), "=r"(c) : "l"(acc[i][p]));
            lo[i] = fmaxf(__uint_as_float(a), 0.0f);
            hi[i] = fmaxf(__uint_as_float(c), 0.0f);
        }
        int ne = n0 + nl0 + 2 * p;
        float4* d0 = reinterpret_cast<float4*>(hb + (size_t)ne * COUT + c0);
        d0[0] = make_float4(lo[0], lo[1], lo[2], lo[3]);
        d0[1] = make_float4(lo[4], lo[5], lo[6], lo[7]);
        float4* d1 = reinterpret_cast<float4*>(hb + (size_t)(ne + 1) * COUT + c0);
        d1[0] = make_float4(hi[0], hi[1], hi[2], hi[3]);
        d1[1] = make_float4(hi[4], hi[5], hi[6], hi[7]);
    }
}

// ---------------------------------------------------------------------------
// Kernel 2: out[b][c][n] = (1/17) * ( sum_{k<16} h[b][:, idx_k] + h[b][:, n] ) + bias[c]
// Warp handles 4 nodes; each lane owns 4 channels (float4) -> gathered rows are
// fully-coalesced 512B reads. Output re-transposed via padded smem tile so the
// [b][c][n] stores are 128B-coalesced along n.
// ---------------------------------------------------------------------------
__global__ void __launch_bounds__(256)
gather_mean_bias_kernel(const int* __restrict__ ei,
                        const float* __restrict__ bias,
                        float* __restrict__ out)
{
    __shared__ __align__(16) float tile[32][132];   // padded: (4i+c)%32 -> <=4-way on read

    const int b    = blockIdx.y;
    const int n0   = blockIdx.x * 32;
    const int t    = threadIdx.x;
    const int lane = t & 31;
    const int w    = t >> 5;                 // warp 0..7, 4 nodes each
    const int nbase = n0 + w * 4;

    const float4* hb = reinterpret_cast<const float4*>(g_h) + (size_t)b * NN * 32;
    const int* eib = ei + (size_t)b * NN * KNBR;   // edge_index[0][b]...

    float4 acc[4];
    int myidx[4];
#pragma unroll
    for (int m = 0; m < 4; m++) {
        acc[m] = make_float4(0.f, 0.f, 0.f, 0.f);
        myidx[m] = (lane < KNBR) ? eib[(size_t)(nbase + m) * KNBR + lane] : 0;
    }

#pragma unroll 4
    for (int k = 0; k < KNBR; k++) {
#pragma unroll
        for (int m = 0; m < 4; m++) {
            int j = __shfl_sync(0xffffffffu, myidx[m], k);
            float4 v = __ldg(&hb[(size_t)j * 32 + lane]);
            acc[m].x += v.x; acc[m].y += v.y; acc[m].z += v.z; acc[m].w += v.w;
        }
    }
    // self loop
#pragma unroll
    for (int m = 0; m < 4; m++) {
        float4 v = __ldg(&hb[(size_t)(nbase + m) * 32 + lane]);
        acc[m].x += v.x; acc[m].y += v.y; acc[m].z += v.z; acc[m].w += v.w;
    }

    const float norm = 1.0f / 17.0f;
    float4 bv = __ldg(reinterpret_cast<const float4*>(bias) + lane);

#pragma unroll
    for (int m = 0; m < 4; m++) {
        float4 r;
        r.x = fmaf(acc[m].x, norm, bv.x);
        r.y = fmaf(acc[m].y, norm, bv.y);
        r.z = fmaf(acc[m].z, norm, bv.z);
        r.w = fmaf(acc[m].w, norm, bv.w);
        *reinterpret_cast<float4*>(&tile[w * 4 + m][lane * 4]) = r;
    }
    __syncthreads();

    // Coalesced write-out: out[b][c][n0..n0+31]
#pragma unroll
    for (int r = 0; r < 16; r++) {
        int e = t + 256 * r;          // 0..4095
        int c = e >> 5;
        int i = e & 31;
        out[((size_t)b * COUT + c) * NN + n0 + i] = tile[i][c];
    }
}

extern "C" void kernel_launch(void* const* d_in, const int* in_sizes, int n_in,
                              void* d_out, int out_size)
{
    const float* x    = (const float*)d_in[0];   // [16,128,4096,1]
    const int*   ei   = (const int*)  d_in[1];   // [2,16,4096,16]
    const float* W    = (const float*)d_in[2];   // [128,128]
    const float* bias = (const float*)d_in[3];   // [1,128,1,1]
    float* out = (float*)d_out;                  // [16,128,4096,1]

    dim3 g1(NN / TILE_N, BB);   // 32 x 16
    gemm_relu_kernel<<<g1, 256>>>(x, W);

    dim3 g2(NN / 32, BB);       // 128 x 16
    gather_mean_bias_kernel<<<g2, 256>>>(ei, bias, out);
}